// round 15
// baseline (speedup 1.0000x reference)
#include <cuda_runtime.h>
#include <cuda_fp16.h>
#include <stdint.h>
#include <math.h>

// ---------------- problem constants ----------------
#define D_    256
#define NH_   8
#define HD_   32
#define B_    8
#define LQ_   3600
#define LIN_  4725
#define ROWS_ (LQ_*B_)       // 28800
#define VROWS_ (B_*LIN_)     // 37800
#define DFF_  1024

// ---------------- fp16 activation arena ----------------
#define SZ_TGT (ROWS_*D_)
#define SZ_SRC (VROWS_*D_)
#define SZ_RC  (ROWS_*D_)
#define SZ_FFN (ROWS_*DFF_)
#define OFF_TGT 0
#define OFF_SRC (OFF_TGT+SZ_TGT)
#define OFF_CTX (OFF_SRC+SZ_SRC)
#define OFF_T   (OFF_CTX+SZ_RC)
#define OFF_MS  (OFF_T+SZ_RC)
#define OFF_TQ  (OFF_MS+SZ_RC)
#define OFF_FFN (OFF_TQ+SZ_RC)
#define ARENA_SZ (OFF_FFN+SZ_FFN)

__device__ __align__(256) __half g_act[ARENA_SZ];
__device__ __align__(256) __half g_tmph[(size_t)ROWS_*D_];

// weight arena (single fp16; sow and aww adjacent -> merged N=288 GEMM)
#define WOFF_IN  0
#define WOFF_OW  (WOFF_IN+768*256)
#define WOFF_VW  (WOFF_OW+256*256)
#define WOFF_SOW (WOFF_VW+256*256)
#define WOFF_AWW (WOFF_SOW+192*256)
#define WOFF_COW (WOFF_AWW+96*256)
#define WOFF_F1  (WOFF_COW+256*256)
#define WOFF_F2  (WOFF_F1+1024*256)
#define WARENA   (WOFF_F2+256*1024)
__device__ __align__(256) __half g_whi[WARENA];

// scratch
__device__ __align__(256) __half g_Q  [(size_t)LQ_*NH_*8*HD_];
__device__ __align__(256) __half g_K  [(size_t)LQ_*NH_*8*HD_];
__device__ __align__(256) __half g_Vv [(size_t)LQ_*NH_*8*HD_];
__device__ __align__(256) __half g_val[(size_t)B_*NH_*LIN_*HD_];
__device__ __align__(256) float g_off[(size_t)ROWS_*192];
__device__ __align__(256) float g_aw [(size_t)ROWS_*96];
__device__ __align__(256) float g_cball[8*1024];

// ---------------- helpers ----------------
__device__ __forceinline__ uint32_t smem_u32(const void* p){
    uint32_t a;
    asm("{ .reg .u64 t; cvta.to.shared.u64 t, %1; cvt.u32.u64 %0, t; }" : "=r"(a) : "l"(p));
    return a;
}

#define LDSM4(r, addr) \
    asm volatile("ldmatrix.sync.aligned.m8n8.x4.shared.b16 {%0,%1,%2,%3}, [%4];" \
        : "=r"((r)[0]), "=r"((r)[1]), "=r"((r)[2]), "=r"((r)[3]) : "r"(addr))

#define MMA16816(d, a, b) \
    asm volatile("mma.sync.aligned.m16n8k16.row.col.f32.f16.f16.f32 " \
        "{%0,%1,%2,%3}, {%4,%5,%6,%7}, {%8,%9}, {%0,%1,%2,%3};" \
        : "+f"((d)[0]), "+f"((d)[1]), "+f"((d)[2]), "+f"((d)[3]) \
        : "r"((a)[0]), "r"((a)[1]), "r"((a)[2]), "r"((a)[3]), "r"((b)[0]), "r"((b)[1]))

#define CPA16(sa, ga) asm volatile("cp.async.cg.shared.global [%0], [%1], 16;" :: "r"(sa), "l"(ga))
#define CPA_COMMIT()  asm volatile("cp.async.commit_group;")

// ---------------- merged preprocessing: cvta + cvtw + column biases ----------------
#define NB_CVTA 16650   // (SZ_TGT+SZ_SRC)/4/256
#define NB_CVTW 968     // WARENA/4/256
#define NB_CB   32      // 8192/256
struct PreArgs {
    const float* W[8]; const float* Bv[8];
    int N[8]; int K[8]; int lim[8];
    const float* qp; const float* tgt; const float* src;
};
__global__ void __launch_bounds__(256) pre_kernel(PreArgs a)
{
    int bid = blockIdx.x, tid = threadIdx.x;
    if (bid < NB_CVTA) {
        int e = (bid * 256 + tid) * 4;
        const float* sp; int dst;
        if (e < SZ_TGT) { sp = a.tgt + e; dst = OFF_TGT + e; }
        else            { sp = a.src + (e - SZ_TGT); dst = OFF_SRC + (e - SZ_TGT); }
        float4 v = *(const float4*)sp;
        __half2 p0 = __floats2half2_rn(v.x, v.y);
        __half2 p1 = __floats2half2_rn(v.z, v.w);
        *(uint2*)(g_act+dst) = make_uint2(*(uint32_t*)&p0, *(uint32_t*)&p1);
    } else if (bid < NB_CVTA + NB_CVTW) {
        int e = ((bid - NB_CVTA) * 256 + tid) * 4;
        const int offs[9] = {0,196608,262144,327680,376832,401408,466944,729088,991232};
        int seg = 0;
        #pragma unroll
        for (int s = 1; s < 8; s++) if (e >= offs[s]) seg = s;
        float4 v = *(const float4*)(a.W[seg] + (e - offs[seg]));
        __half2 p0 = __floats2half2_rn(v.x, v.y);
        __half2 p1 = __floats2half2_rn(v.z, v.w);
        *(uint2*)(g_whi+e) = make_uint2(*(uint32_t*)&p0, *(uint32_t*)&p1);
    } else {
        int g = (bid - NB_CVTA - NB_CVTW) * 256 + tid;   // 0..8191
        int seg = g >> 10, n = g & 1023;
        if (n >= a.N[seg]) return;
        float v = a.Bv[seg][n];
        if (n < a.lim[seg]) {
            const float* w = a.W[seg] + (size_t)n * a.K[seg];
            float acc = 0.f;
            for (int k = 0; k < a.K[seg]; k += 4) {
                float4 wv = *(const float4*)(w + k);
                float4 qv = *(const float4*)(a.qp + k);
                acc += wv.x*qv.x + wv.y*qv.y + wv.z*qv.z + wv.w*qv.w;
            }
            v += acc;
        }
        int dst = (seg == 4) ? (3*1024 + 192 + n) : (seg*1024 + n);
        g_cball[dst] = v;
    }
}

// ---------------- mma.sync GEMM: C[m,n] = A[m,:]·W[n,:] + cb[n] ----------------
// single fp16, CTA tile 128x256, 8 warps 2Mx4N, warp tile 64x64, BK=32, 3-stage cp.async.
// Stage (80B rows): A(128 rows)@0, W(256 rows)@10240; stage stride 30720.
// MODE 1: relu->fp16   MODE 2: QKV scatter (fp16)   MODE 3: value scatter (fp16)
// MODE 4: off/aw split scatter (fp32)   MODE 5: plain fp16 store
#define GSMEM (3*30720 + 1024)

template<int MODE>
__global__ void __launch_bounds__(256)
gemm_mma(const __half* __restrict__ A, const __half* __restrict__ W,
         __half* __restrict__ Ch,
         const float* __restrict__ cb, int M, int N, int K)
{
    extern __shared__ __align__(16) char smc[];
    uint32_t sb = smem_u32(smc);
    float* biass = (float*)(smc + 92160);
    int tid = threadIdx.x, wid = tid >> 5, lane = tid & 31;
    int m0 = blockIdx.x * 128, n0 = blockIdx.y * 256;

    biass[tid] = cb[n0 + tid];

    float acc[4][8][4];
    #pragma unroll
    for (int i = 0; i < 4; i++)
        #pragma unroll
        for (int j = 0; j < 8; j++)
            #pragma unroll
            for (int e = 0; e < 4; e++) acc[i][j][e] = 0.f;

    const int NC = K >> 5;
    const int wm = (wid & 1) * 64, wn = (wid >> 1) * 64;

    auto stage_load = [&](int c, int st) {
        size_t kb = (size_t)c * 32;
        uint32_t base = sb + st * 30720;
        #pragma unroll
        for (int i = 0; i < 6; i++) {
            int chunk = tid + i * 256;            // 0..1535
            if (chunk < 512) {
                int row = chunk >> 2, cc = chunk & 3;
                uint32_t sa = base + row*80 + cc*16;
                int gm = m0 + row;
                if (gm < M) CPA16(sa, A + ((size_t)gm * K + kb + cc*8));
                else        asm volatile("st.shared.v4.b32 [%0], {%1,%1,%1,%1};" :: "r"(sa), "r"(0u));
            } else {
                int w = chunk - 512;              // 0..1023
                int row = w >> 2, cc = w & 3;
                uint32_t sa = base + 10240 + row*80 + cc*16;
                int gn = n0 + row;
                if (gn < N) CPA16(sa, W + ((size_t)gn * K + kb + cc*8));
                else        asm volatile("st.shared.v4.b32 [%0], {%1,%1,%1,%1};" :: "r"(sa), "r"(0u));
            }
        }
        CPA_COMMIT();
    };

    stage_load(0, 0);
    if (NC > 1) stage_load(1, 1);

    for (int c = 0; c < NC; c++) {
        if (c + 2 < NC) {
            stage_load(c + 2, (c + 2) % 3);
            asm volatile("cp.async.wait_group 2;");
        } else if (c + 1 < NC) {
            asm volatile("cp.async.wait_group 1;");
        } else {
            asm volatile("cp.async.wait_group 0;");
        }
        __syncthreads();

        uint32_t ab = sb + (c % 3) * 30720;
        int g = lane >> 3, li = lane & 7;
        #pragma unroll
        for (int k16 = 0; k16 < 2; k16++) {
            uint32_t aH[4][4], bH[8][2];
            #pragma unroll
            for (int mt = 0; mt < 4; mt++) {
                int row = wm + mt*16 + (g & 1)*8 + li;
                uint32_t ad = ab + row*80 + k16*32 + (g >> 1)*16;
                LDSM4(aH[mt], ad);
            }
            #pragma unroll
            for (int np = 0; np < 4; np++) {
                int row = wn + np*16 + ((lane >= 16) ? 8 : 0) + li;
                uint32_t bd = ab + 10240 + row*80 + k16*32 + ((lane >> 3) & 1)*16;
                uint32_t t4[4];
                LDSM4(t4, bd);
                bH[np*2][0] = t4[0]; bH[np*2][1] = t4[1];
                bH[np*2+1][0] = t4[2]; bH[np*2+1][1] = t4[3];
            }
            #pragma unroll
            for (int mt = 0; mt < 4; mt++)
                #pragma unroll
                for (int nt = 0; nt < 8; nt++)
                    MMA16816(acc[mt][nt], aH[mt], bH[nt]);
        }
        __syncthreads();
    }

    // ---------------- epilogue ----------------
    int qr = lane >> 2, qc = (lane & 3) * 2;
    #pragma unroll
    for (int mt = 0; mt < 4; mt++) {
        #pragma unroll
        for (int half_ = 0; half_ < 2; half_++) {
            int m = m0 + wm + mt*16 + half_*8 + qr;
            if (m >= M) continue;
            #pragma unroll
            for (int nt = 0; nt < 8; nt++) {
                int cl = wn + nt*8 + qc;
                int n = n0 + cl;
                if (n >= N) continue;
                float v0 = acc[mt][nt][half_*2 + 0] + biass[cl];
                float v1 = acc[mt][nt][half_*2 + 1] + biass[cl + 1];
                if (MODE == 5) {
                    *(__half2*)(Ch + (size_t)m * N + n) = __floats2half2_rn(v0, v1);
                } else if (MODE == 1) {
                    __half2 p = __floats2half2_rn(fmaxf(v0, 0.f), fmaxf(v1, 0.f));
                    *(__half2*)(Ch + (size_t)m * N + n) = p;
                } else if (MODE == 2) {
                    int lq = m >> 3, b = m & 7;
                    int part = n >> 8, h = (n >> 5) & 7, d = n & 31;
                    size_t o = ((((size_t)lq * NH_ + h) * 8) + b) * HD_ + d;
                    __half* dstb = (part == 0) ? g_Q : (part == 1) ? g_K : g_Vv;
                    *(__half2*)(dstb + o) = __floats2half2_rn(v0, v1);
                } else if (MODE == 3) {
                    int b = m / LIN_, lin = m - b * LIN_;
                    int h = n >> 5, d = n & 31;
                    size_t o = (((size_t)(b*NH_ + h)) * LIN_ + lin) * HD_ + d;
                    *(__half2*)(g_val + o) = __floats2half2_rn(v0, v1);
                } else { // MODE 4
                    if (n < 192)
                        *(float2*)(g_off + (size_t)m * 192 + n) = make_float2(v0, v1);
                    else
                        *(float2*)(g_aw + (size_t)m * 96 + (n - 192)) = make_float2(v0, v1);
                }
            }
        }
    }
}

// ---------------- self-attention over the 8-token axis ----------------
#define ALQ 2
__global__ void __launch_bounds__(128)
attn_kernel()
{
    __shared__ float Ks[ALQ * NH_ * 8 * HD_];
    __shared__ float Vs[ALQ * NH_ * 8 * HD_];

    int lq0 = blockIdx.x * ALQ;
    int t = threadIdx.x;

    const uint4* kg = (const uint4*)(g_K  + (size_t)lq0 * NH_ * 8 * HD_);
    const uint4* vg = (const uint4*)(g_Vv + (size_t)lq0 * NH_ * 8 * HD_);
    #pragma unroll
    for (int f = 0; f < (ALQ * NH_ * 8 * HD_ / 8) / 128; f++) {
        int idx = f * 128 + t;
        uint4 kv = kg[idx], vv = vg[idx];
        const __half2* kh = (const __half2*)&kv;
        const __half2* vh = (const __half2*)&vv;
        float* kd = Ks + idx * 8;
        float* vd = Vs + idx * 8;
        #pragma unroll
        for (int j = 0; j < 4; j++) {
            float2 a = __half22float2(kh[j]); kd[2*j] = a.x; kd[2*j+1] = a.y;
            float2 b = __half22float2(vh[j]); vd[2*j] = b.x; vd[2*j+1] = b.y;
        }
    }
    __syncthreads();

    int lql = t >> 6;
    int r   = t & 63;
    int h   = r >> 3;
    int s   = r & 7;
    int lq  = lq0 + lql;

    const float scale = 0.17677669529663687f;
    float qr[HD_];
    {
        const uint4* Qp = (const uint4*)(g_Q + ((((size_t)lq * NH_ + h) * 8) + s) * HD_);
        #pragma unroll
        for (int i = 0; i < 4; i++) {
            uint4 q4 = Qp[i];
            const __half2* qh = (const __half2*)&q4;
            #pragma unroll
            for (int j = 0; j < 4; j++) {
                float2 a = __half22float2(qh[j]);
                qr[i*8 + 2*j] = a.x; qr[i*8 + 2*j + 1] = a.y;
            }
        }
    }

    const float* Kt = Ks + (lql * NH_ + h) * 8 * HD_;
    const float* Vt = Vs + (lql * NH_ + h) * 8 * HD_;

    float logit[8];
    float mx = -1e30f;
    #pragma unroll
    for (int j = 0; j < 8; j++) {
        float acc = 0.f;
        const float* kp = Kt + j * HD_;
        #pragma unroll
        for (int d = 0; d < HD_; d++) acc = fmaf(qr[d], kp[d], acc);
        logit[j] = acc * scale;
        mx = fmaxf(mx, logit[j]);
    }
    float sum = 0.f;
    #pragma unroll
    for (int j = 0; j < 8; j++) { logit[j] = __expf(logit[j] - mx); sum += logit[j]; }
    float inv = 1.f / sum;

    float accv[HD_];
    #pragma unroll
    for (int d = 0; d < HD_; d++) accv[d] = 0.f;
    #pragma unroll
    for (int j = 0; j < 8; j++) {
        float p = logit[j] * inv;
        const float* vp = Vt + j * HD_;
        #pragma unroll
        for (int d = 0; d < HD_; d++) accv[d] = fmaf(p, vp[d], accv[d]);
    }

    __half* oh = g_act + OFF_CTX + ((size_t)(lq * B_ + s)) * D_ + h * HD_;
    #pragma unroll
    for (int d = 0; d < HD_; d += 2)
        *(__half2*)(oh + d) = __floats2half2_rn(accv[d], accv[d+1]);
}

// ---------------- LayerNorm(x1 + x2) on fp16 inputs ----------------
__global__ void __launch_bounds__(256)
ln_kernel(const __half* __restrict__ x1, const __half* __restrict__ x2,
          const float* __restrict__ gam, const float* __restrict__ bet,
          __half* __restrict__ oh, float* __restrict__ of)
{
    int gwarp = (blockIdx.x * blockDim.x + threadIdx.x) >> 5;
    int lane  = threadIdx.x & 31;
    if (gwarp >= ROWS_) return;
    size_t base = (size_t)gwarp * D_ + lane * 8;

    float v[8];
    {
        uint4 a4 = *(const uint4*)(x1 + base);
        uint4 b4 = *(const uint4*)(x2 + base);
        const __half2* ah = (const __half2*)&a4;
        const __half2* bh = (const __half2*)&b4;
        #pragma unroll
        for (int j = 0; j < 4; j++) {
            float2 a = __half22float2(ah[j]);
            float2 b = __half22float2(bh[j]);
            v[2*j]   = a.x + b.x;
            v[2*j+1] = a.y + b.y;
        }
    }
    float s = 0.f, ss = 0.f;
    #pragma unroll
    for (int j = 0; j < 8; j++) { s += v[j]; ss += v[j]*v[j]; }
    #pragma unroll
    for (int o = 16; o > 0; o >>= 1) {
        s  += __shfl_xor_sync(0xffffffffu, s,  o);
        ss += __shfl_xor_sync(0xffffffffu, ss, o);
    }
    float mean = s * (1.f/256.f);
    float var  = ss * (1.f/256.f) - mean*mean;
    float rstd = rsqrtf(var + 1e-5f);

    int c = lane * 8;
    float4 g0 = *(const float4*)(gam + c);
    float4 g1 = *(const float4*)(gam + c + 4);
    float4 e0 = *(const float4*)(bet + c);
    float4 e1 = *(const float4*)(bet + c + 4);
    float ov[8];
    ov[0] = (v[0]-mean)*rstd*g0.x + e0.x;
    ov[1] = (v[1]-mean)*rstd*g0.y + e0.y;
    ov[2] = (v[2]-mean)*rstd*g0.z + e0.z;
    ov[3] = (v[3]-mean)*rstd*g0.w + e0.w;
    ov[4] = (v[4]-mean)*rstd*g1.x + e1.x;
    ov[5] = (v[5]-mean)*rstd*g1.y + e1.y;
    ov[6] = (v[6]-mean)*rstd*g1.z + e1.z;
    ov[7] = (v[7]-mean)*rstd*g1.w + e1.w;

    if (oh) {
        __half2 p0 = __floats2half2_rn(ov[0], ov[1]);
        __half2 p1 = __floats2half2_rn(ov[2], ov[3]);
        __half2 p2 = __floats2half2_rn(ov[4], ov[5]);
        __half2 p3 = __floats2half2_rn(ov[6], ov[7]);
        *(uint4*)(oh + base) = make_uint4(*(uint32_t*)&p0, *(uint32_t*)&p1,
                                          *(uint32_t*)&p2, *(uint32_t*)&p3);
    }
    if (of) {
        *(float4*)(of + base)     = make_float4(ov[0], ov[1], ov[2], ov[3]);
        *(float4*)(of + base + 4) = make_float4(ov[4], ov[5], ov[6], ov[7]);
    }
}

// ---------------- MS-deformable sampling: 2 points per half-warp, half2 channels ----
__device__ __forceinline__ float2 samp2(const __half* __restrict__ vb,
                                        int y, int x, int W, int cl)
{
    if (x < 0 || x >= W || y < 0 || y >= W) return make_float2(0.f, 0.f);
    return __half22float2(*(const __half2*)(vb + ((size_t)(y * W + x)) * HD_ + 2*cl));
}

__global__ void __launch_bounds__(256)
msdeform_kernel()
{
    int gw = (blockIdx.x * blockDim.x + threadIdx.x) >> 5;
    int lane = threadIdx.x & 31;
    if (gw >= ROWS_ * NH_) return;
    int i = gw >> 3, h = gw & 7;
    int s = i >> 3, b = i & 7;
    int hv = lane >> 4;
    int cl = lane & 15;

    float rx = ((s % 60) + 0.5f) * (1.f/60.f);
    float ry = ((s / 60) + 0.5f) * (1.f/60.f);

    const float* awp = g_aw + (size_t)i * 96 + h * 12;
    float mx = -1e30f;
    #pragma unroll
    for (int t = 0; t < 12; t++) mx = fmaxf(mx, awp[t]);
    float sm = 0.f;
    #pragma unroll
    for (int t = 0; t < 12; t++) sm += __expf(awp[t] - mx);
    float inv = 1.f / sm;

    const float* offp = g_off + (size_t)i * 192 + h * 24;
    const __half* vbase = g_val + (((size_t)(b*NH_ + h)) * LIN_) * HD_;

    float ax = 0.f, ay = 0.f;
    #pragma unroll
    for (int j = 0; j < 6; j++) {
        int t = 2*j + hv;
        int l = t >> 2;
        int Wl = 60 >> l;
        int St = (l >= 1 ? 3600 : 0) + (l >= 2 ? 900 : 0);
        float fWl = (float)Wl;
        float ox = offp[2*t], oy = offp[2*t + 1];
        float x = (rx + ox / fWl) * fWl - 0.5f;
        float y = (ry + oy / fWl) * fWl - 0.5f;
        float fx0 = floorf(x), fy0 = floorf(y);
        float fx = x - fx0, fy = y - fy0;
        int x0 = (int)fx0, y0 = (int)fy0;
        float a = __expf(awp[t] - mx) * inv;
        const __half* vb = vbase + (size_t)St * HD_;
        float2 s00 = samp2(vb, y0,   x0,   Wl, cl);
        float2 s01 = samp2(vb, y0,   x0+1, Wl, cl);
        float2 s10 = samp2(vb, y0+1, x0,   Wl, cl);
        float2 s11 = samp2(vb, y0+1, x0+1, Wl, cl);
        float w00 = (1.f-fx)*(1.f-fy), w01 = fx*(1.f-fy);
        float w10 = (1.f-fx)*fy,       w11 = fx*fy;
        float bx = s00.x*w00 + s01.x*w01 + s10.x*w10 + s11.x*w11;
        float by = s00.y*w00 + s01.y*w01 + s10.y*w10 + s11.y*w11;
        ax = fmaf(a, bx, ax);
        ay = fmaf(a, by, ay);
    }
    ax += __shfl_xor_sync(0xffffffffu, ax, 16);
    ay += __shfl_xor_sync(0xffffffffu, ay, 16);
    if (hv == 0)
        *(__half2*)(g_act + OFF_MS + (size_t)i * D_ + h * HD_ + 2*cl) = __floats2half2_rn(ax, ay);
}

// ---------------- host orchestration ----------------
extern "C" void kernel_launch(void* const* d_in, const int* in_sizes, int n_in,
                              void* d_out, int out_size)
{
    (void)in_sizes; (void)n_in; (void)out_size;
    const float* tgt  = (const float*)d_in[0];
    const float* qp   = (const float*)d_in[1];
    const float* src  = (const float*)d_in[2];
    const float* in_w = (const float*)d_in[5];
    const float* in_b = (const float*)d_in[6];
    const float* ow   = (const float*)d_in[7];
    const float* ob   = (const float*)d_in[8];
    const float* sow  = (const float*)d_in[9];
    const float* sob  = (const float*)d_in[10];
    const float* aww  = (const float*)d_in[11];
    const float* awb  = (const float*)d_in[12];
    const float* vw   = (const float*)d_in[13];
    const float* vb   = (const float*)d_in[14];
    const float* cow  = (const float*)d_in[15];
    const float* cob  = (const float*)d_in[16];
    const float* ln1g = (const float*)d_in[17];
    const float* ln1b = (const float*)d_in[18];
    const float* ln2g = (const float*)d_in[19];
    const float* ln2b = (const float*)d_in[20];
    const float* ln3g = (const float*)d_in[21];
    const float* ln3b = (const float*)d_in[22];
    const float* f1w  = (const float*)d_in[23];
    const float* f1b  = (const float*)d_in[24];
    const float* f2w  = (const float*)d_in[25];
    const float* f2b  = (const float*)d_in[26];
    float* out = (float*)d_out;

    __half *act, *whi, *tmph;
    float *cbp;
    cudaGetSymbolAddress((void**)&act,  g_act);
    cudaGetSymbolAddress((void**)&whi,  g_whi);
    cudaGetSymbolAddress((void**)&tmph, g_tmph);
    cudaGetSymbolAddress((void**)&cbp,  g_cball);

    cudaFuncSetAttribute(gemm_mma<1>, cudaFuncAttributeMaxDynamicSharedMemorySize, GSMEM);
    cudaFuncSetAttribute(gemm_mma<2>, cudaFuncAttributeMaxDynamicSharedMemorySize, GSMEM);
    cudaFuncSetAttribute(gemm_mma<3>, cudaFuncAttributeMaxDynamicSharedMemorySize, GSMEM);
    cudaFuncSetAttribute(gemm_mma<4>, cudaFuncAttributeMaxDynamicSharedMemorySize, GSMEM);
    cudaFuncSetAttribute(gemm_mma<5>, cudaFuncAttributeMaxDynamicSharedMemorySize, GSMEM);

    // ---- merged preprocessing ----
    PreArgs pa;
    pa.W[0]=in_w; pa.Bv[0]=in_b; pa.N[0]=768;  pa.K[0]=256;  pa.lim[0]=512;
    pa.W[1]=ow;   pa.Bv[1]=ob;   pa.N[1]=256;  pa.K[1]=256;  pa.lim[1]=0;
    pa.W[2]=vw;   pa.Bv[2]=vb;   pa.N[2]=256;  pa.K[2]=256;  pa.lim[2]=0;
    pa.W[3]=sow;  pa.Bv[3]=sob;  pa.N[3]=192;  pa.K[3]=256;  pa.lim[3]=192;
    pa.W[4]=aww;  pa.Bv[4]=awb;  pa.N[4]=96;   pa.K[4]=256;  pa.lim[4]=96;
    pa.W[5]=cow;  pa.Bv[5]=cob;  pa.N[5]=256;  pa.K[5]=256;  pa.lim[5]=0;
    pa.W[6]=f1w;  pa.Bv[6]=f1b;  pa.N[6]=1024; pa.K[6]=256;  pa.lim[6]=0;
    pa.W[7]=f2w;  pa.Bv[7]=f2b;  pa.N[7]=256;  pa.K[7]=1024; pa.lim[7]=0;
    pa.qp = qp; pa.tgt = tgt; pa.src = src;
    pre_kernel<<<NB_CVTA + NB_CVTW + NB_CB, 256>>>(pa);

    const int MT  = 225;   // 28800/128
    const int VMT = 296;   // ceil(37800/128)

    // 1) QKV projection (qp folded into Q/K bias), fp16 scatter  (N=768 -> 3 y-tiles)
    gemm_mma<2><<<dim3(MT, 3), 256, GSMEM>>>(act+OFF_TGT, whi+WOFF_IN,
                                             nullptr, cbp+0*1024, ROWS_, 768, 256);
    // 2) tiny self-attention
    attn_kernel<<<LQ_/ALQ, 128>>>();
    // 3) out projection (fp16) + ln2 (fp16 residual)
    gemm_mma<5><<<dim3(MT, 1), 256, GSMEM>>>(act+OFF_CTX, whi+WOFF_OW,
                                             tmph, cbp+1*1024, ROWS_, 256, 256);
    ln_kernel<<<ROWS_/8, 256>>>(act+OFF_TGT, tmph, ln2g, ln2b, act+OFF_T, nullptr);
    // 4) value projection (fp16 scatter) + merged off/aw GEMM (N=288 -> 2 y-tiles)
    gemm_mma<3><<<dim3(VMT, 1), 256, GSMEM>>>(act+OFF_SRC, whi+WOFF_VW,
                                              nullptr, cbp+2*1024, VROWS_, 256, 256);
    gemm_mma<4><<<dim3(MT, 2), 256, GSMEM>>>(act+OFF_T, whi+WOFF_SOW,
                                             nullptr, cbp+3*1024, ROWS_, 288, 256);
    // 5) sampling + cross projection + ln1
    msdeform_kernel<<<ROWS_, 256>>>();
    gemm_mma<5><<<dim3(MT, 1), 256, GSMEM>>>(act+OFF_MS, whi+WOFF_COW,
                                             tmph, cbp+5*1024, ROWS_, 256, 256);
    ln_kernel<<<ROWS_/8, 256>>>(act+OFF_T, tmph, ln1g, ln1b, act+OFF_TQ, nullptr);
    // 6) FFN + ln3 (final fp32 output)
    gemm_mma<1><<<dim3(MT, 4), 256, GSMEM>>>(act+OFF_TQ, whi+WOFF_F1,
                                             act+OFF_FFN, cbp+6*1024, ROWS_, 1024, 256);
    gemm_mma<5><<<dim3(MT, 1), 256, GSMEM>>>(act+OFF_FFN, whi+WOFF_F2,
                                             tmph, cbp+7*1024, ROWS_, 256, 1024);
    ln_kernel<<<ROWS_/8, 256>>>(act+OFF_TQ, tmph, ln3g, ln3b, nullptr, out);
}